// round 4
// baseline (speedup 1.0000x reference)
#include <cuda_runtime.h>
#include <math_constants.h>

// Problem constants (fixed by the reference)
#define Nn 100000
#define Ee 3200000
#define EN (Ee + Nn)      // edges + self loops
#define Hh 32
#define Ff 128
#define Bb 256
#define D1 1024
#define D2 512
#define D3 4

// ---------------- scratch (static device globals; no allocation) -----------
__device__ float        d_xl[Nn * Hh];       // x @ Wl
__device__ float        d_xr[Nn * Hh];       // x @ Wr
__device__ float        d_e[EN];             // edge scores, then exp(p)
__device__ unsigned int d_m[Nn];             // segment max (encoded float)
__device__ float        d_z[Nn];             // segment sum
__device__ float        d_node[Nn * Hh];     // aggregated node output
__device__ unsigned int d_g[Bb * Hh];        // pooled max per graph (encoded)
__device__ float        d_h1[Bb * D1];
__device__ float        d_h2[Bb * D2];

// order-preserving float<->unsigned encoding for atomicMax on floats
__device__ __forceinline__ unsigned int fenc(float f) {
    unsigned int u = __float_as_uint(f);
    return u ^ ((unsigned int)((int)u >> 31) | 0x80000000u);
}
__device__ __forceinline__ float fdec(unsigned int e) {
    unsigned int mask = ((int)e < 0) ? 0x80000000u : 0xFFFFFFFFu;
    return __uint_as_float(e ^ mask);
}

// fenc(-inf) = bits(0xFF800000) negative -> ~bits = 0x007FFFFF
#define ENC_NEG_INF 0x007FFFFFu

// ---------------- kernels ---------------------------------------------------

// init scratch that is accumulated into
__global__ void k_init() {
    int i = blockIdx.x * blockDim.x + threadIdx.x;
    if (i < Nn * Hh) d_node[i] = 0.0f;
    if (i < Nn) { d_m[i] = ENC_NEG_INF; d_z[i] = 0.0f; }
    if (i < Bb * Hh) d_g[i] = ENC_NEG_INF;
}

// xl = x @ Wl, xr = x @ Wr. 8 nodes per block (one per warp), lane = h.
__global__ void __launch_bounds__(256) k_transform(
    const float* __restrict__ x,
    const float* __restrict__ Wl,
    const float* __restrict__ Wr)
{
    __shared__ float sWl[Ff * Hh];
    __shared__ float sWr[Ff * Hh];
    __shared__ float sx[8 * Ff];

    int t = threadIdx.x;
    for (int i = t; i < Ff * Hh; i += 256) { sWl[i] = Wl[i]; sWr[i] = Wr[i]; }

    int nodeBase = blockIdx.x * 8;  // N divisible by 8
    const float4* x4 = (const float4*)(x + (size_t)nodeBase * Ff);
    float4* sx4 = (float4*)sx;
    for (int i = t; i < (8 * Ff) / 4; i += 256) sx4[i] = x4[i];
    __syncthreads();

    int lane  = t & 31;
    int local = t >> 5;
    int node  = nodeBase + local;

    float accL = 0.0f, accR = 0.0f;
    const float4* xrow = (const float4*)(sx + local * Ff);
#pragma unroll
    for (int k4 = 0; k4 < Ff / 4; k4++) {
        float4 xv = xrow[k4];
        int k = k4 * 4;
        accL += xv.x * sWl[(k + 0) * Hh + lane];
        accL += xv.y * sWl[(k + 1) * Hh + lane];
        accL += xv.z * sWl[(k + 2) * Hh + lane];
        accL += xv.w * sWl[(k + 3) * Hh + lane];
        accR += xv.x * sWr[(k + 0) * Hh + lane];
        accR += xv.y * sWr[(k + 1) * Hh + lane];
        accR += xv.z * sWr[(k + 2) * Hh + lane];
        accR += xv.w * sWr[(k + 3) * Hh + lane];
    }
    d_xl[node * Hh + lane] = accL;
    d_xr[node * Hh + lane] = accR;
}

// pass 1: e = att . leaky_relu(xl[src] + xr[dst]); segment max into d_m.
// one warp per edge; lane = h.
__global__ void __launch_bounds__(256) k_edge1(
    const int* __restrict__ ei, const float* __restrict__ att)
{
    int widx = (int)((blockIdx.x * (unsigned)blockDim.x + threadIdx.x) >> 5);
    int lane = threadIdx.x & 31;
    if (widx >= EN) return;

    int src, dst;
    if (widx < Ee) { src = __ldg(&ei[widx]); dst = __ldg(&ei[Ee + widx]); }
    else           { src = dst = widx - Ee; }

    float a = d_xl[src * Hh + lane];
    float b = d_xr[dst * Hh + lane];
    float s = a + b;
    s = (s >= 0.0f) ? s : 0.2f * s;
    s *= __ldg(&att[lane]);
#pragma unroll
    for (int off = 16; off; off >>= 1) s += __shfl_xor_sync(0xFFFFFFFFu, s, off);

    if (lane == 0) {
        d_e[widx] = s;
        atomicMax(&d_m[dst], fenc(s));
    }
}

// pass 2: p = exp(e - m[dst]); z[dst] += p. one thread per edge.
__global__ void __launch_bounds__(256) k_edge2(const int* __restrict__ ei) {
    int i = blockIdx.x * blockDim.x + threadIdx.x;
    if (i >= EN) return;
    int dst = (i < Ee) ? __ldg(&ei[Ee + i]) : (i - Ee);
    float p = expf(d_e[i] - fdec(d_m[dst]));
    d_e[i] = p;
    atomicAdd(&d_z[dst], p);
}

// pass 3: node_out[dst] += (p / z[dst]) * xl[src]. one warp per edge.
__global__ void __launch_bounds__(256) k_edge3(const int* __restrict__ ei) {
    int widx = (int)((blockIdx.x * (unsigned)blockDim.x + threadIdx.x) >> 5);
    int lane = threadIdx.x & 31;
    if (widx >= EN) return;

    int src, dst;
    if (widx < Ee) { src = __ldg(&ei[widx]); dst = __ldg(&ei[Ee + widx]); }
    else           { src = dst = widx - Ee; }

    float alpha = d_e[widx] / d_z[dst];
    atomicAdd(&d_node[dst * Hh + lane], alpha * d_xl[src * Hh + lane]);
}

// global max pool over graphs (bias folded in later; max(x+c)=max(x)+c)
__global__ void __launch_bounds__(256) k_pool(const int* __restrict__ batch) {
    int i = blockIdx.x * blockDim.x + threadIdx.x;
    if (i >= Nn * Hh) return;
    int node = i >> 5;
    int h = i & 31;
    int bg = __ldg(&batch[node]);
    atomicMax(&d_g[bg * Hh + h], fenc(d_node[i]));
}

// h1 = relu((g + bias) @ W1 + b1)
__global__ void __launch_bounds__(1024) k_mlp1(
    const float* __restrict__ W1, const float* __restrict__ b1,
    const float* __restrict__ bias)
{
    __shared__ float sg[Hh];
    int b = blockIdx.x;
    int j = threadIdx.x;
    if (j < Hh) sg[j] = fdec(d_g[b * Hh + j]) + bias[j];
    __syncthreads();
    float acc = b1[j];
#pragma unroll
    for (int k = 0; k < Hh; k++) acc += sg[k] * W1[k * D1 + j];
    d_h1[b * D1 + j] = fmaxf(acc, 0.0f);
}

// h2 = relu(h1 @ W2 + b2); 4 rows per block for W2 reuse
#define R2 4
__global__ void __launch_bounds__(512) k_mlp2(
    const float* __restrict__ W2, const float* __restrict__ b2)
{
    __shared__ float sh[R2 * D1];
    int j = threadIdx.x;                 // output column (512)
    int rb = blockIdx.x * R2;            // row base (64 blocks)
    for (int i = j; i < R2 * D1; i += 512) sh[i] = d_h1[rb * D1 + i];
    __syncthreads();

    float acc[R2];
#pragma unroll
    for (int r = 0; r < R2; r++) acc[r] = b2[j];

    const float4* sh4 = (const float4*)sh;
#pragma unroll 4
    for (int k4 = 0; k4 < D1 / 4; k4++) {
        int k = k4 * 4;
        float w0 = W2[(k + 0) * D2 + j];
        float w1 = W2[(k + 1) * D2 + j];
        float w2 = W2[(k + 2) * D2 + j];
        float w3 = W2[(k + 3) * D2 + j];
#pragma unroll
        for (int r = 0; r < R2; r++) {
            float4 s = sh4[r * (D1 / 4) + k4];
            acc[r] += s.x * w0 + s.y * w1 + s.z * w2 + s.w * w3;
        }
    }
#pragma unroll
    for (int r = 0; r < R2; r++) d_h2[(rb + r) * D2 + j] = fmaxf(acc[r], 0.0f);
}

// out = h2 @ W3 + b3; one block per graph row, one warp per output col
__global__ void __launch_bounds__(128) k_mlp3(
    const float* __restrict__ W3, const float* __restrict__ b3,
    float* __restrict__ out)
{
    int b = blockIdx.x;
    int w = threadIdx.x >> 5;   // 0..3
    int lane = threadIdx.x & 31;
    float acc = 0.0f;
#pragma unroll
    for (int k = lane; k < D2; k += 32)
        acc += d_h2[b * D2 + k] * W3[k * D3 + w];
#pragma unroll
    for (int off = 16; off; off >>= 1) acc += __shfl_xor_sync(0xFFFFFFFFu, acc, off);
    if (lane == 0) out[b * D3 + w] = acc + b3[w];
}

// ---------------- launch -----------------------------------------------------
extern "C" void kernel_launch(void* const* d_in, const int* in_sizes, int n_in,
                              void* d_out, int out_size)
{
    const float* x    = (const float*)d_in[0];
    const int*   ei   = (const int*)  d_in[1];
    const int*   batch= (const int*)  d_in[2];
    const float* Wl   = (const float*)d_in[3];
    const float* Wr   = (const float*)d_in[4];
    const float* att  = (const float*)d_in[5];
    const float* bias = (const float*)d_in[6];
    const float* W1   = (const float*)d_in[7];
    const float* b1   = (const float*)d_in[8];
    const float* W2   = (const float*)d_in[9];
    const float* b2   = (const float*)d_in[10];
    const float* W3   = (const float*)d_in[11];
    const float* b3   = (const float*)d_in[12];
    float* out = (float*)d_out;

    // init accumulators
    k_init<<<(Nn * Hh + 255) / 256, 256>>>();

    // node transforms
    k_transform<<<Nn / 8, 256>>>(x, Wl, Wr);

    // edge softmax + aggregate (3 passes)
    int warpBlocks = (EN + 7) / 8;            // 8 warps (edges) per 256-thread block
    k_edge1<<<warpBlocks, 256>>>(ei, att);
    k_edge2<<<(EN + 255) / 256, 256>>>(ei);
    k_edge3<<<warpBlocks, 256>>>(ei);

    // pool + MLP head
    k_pool<<<(Nn * Hh + 255) / 256, 256>>>(batch);
    k_mlp1<<<Bb, D1>>>(W1, b1, bias);
    k_mlp2<<<Bb / R2, 512>>>(W2, b2);
    k_mlp3<<<Bb, 128>>>(W3, b3, out);
}

// round 5
// speedup vs baseline: 2.0041x; 2.0041x over previous
#include <cuda_runtime.h>
#include <math_constants.h>

// Problem constants (fixed by the reference)
#define Nn 100000
#define Ee 3200000
#define EN (Ee + Nn)      // edges + self loops
#define Hh 32
#define Ff 128
#define Bb 256
#define D1 1024
#define D2 512
#define D3 4

// ---------------- scratch (static device globals; no allocation) -----------
__device__ float        d_xl[Nn * Hh];       // x @ Wl
__device__ float        d_xr[Nn * Hh];       // x @ Wr
__device__ int          d_deg[Nn];           // in-degree incl. self loop
__device__ int          d_rowstart[Nn];      // CSR row offsets
__device__ int          d_cursor[Nn];        // fill cursors
__device__ int          d_csrc[EN];          // CSR source indices (by dst)
__device__ unsigned int d_g[Bb * Hh];        // pooled max per graph (encoded)
__device__ float        d_h1[Bb * D1];
__device__ float        d_h2[Bb * D2];

// order-preserving float<->unsigned encoding for atomicMax on floats
__device__ __forceinline__ unsigned int fenc(float f) {
    unsigned int u = __float_as_uint(f);
    return u ^ ((unsigned int)((int)u >> 31) | 0x80000000u);
}
__device__ __forceinline__ float fdec(unsigned int e) {
    unsigned int mask = ((int)e < 0) ? 0x80000000u : 0xFFFFFFFFu;
    return __uint_as_float(e ^ mask);
}
#define ENC_NEG_INF 0x007FFFFFu

// ---------------- kernels ---------------------------------------------------

// init: deg=1 (self loop), pooled max = -inf
__global__ void k_init() {
    int i = blockIdx.x * blockDim.x + threadIdx.x;
    if (i < Nn) d_deg[i] = 1;
    if (i < Bb * Hh) d_g[i] = ENC_NEG_INF;
}

// degree histogram over real edges (RED, no return value)
__global__ void __launch_bounds__(256) k_count(const int* __restrict__ ei) {
    int i = blockIdx.x * blockDim.x + threadIdx.x;
    if (i < Ee) atomicAdd(&d_deg[__ldg(&ei[Ee + i])], 1);
}

// single-block exclusive scan of d_deg; also place self-loop at slot 0 of
// each row and initialize the fill cursor to slot 1.
__global__ void __launch_bounds__(1024) k_scan() {
    __shared__ int warpsum[32];
    __shared__ int s_carry;
    int t = threadIdx.x, lane = t & 31, w = t >> 5;
    if (t == 0) s_carry = 0;
    __syncthreads();
    for (int base = 0; base < Nn; base += 1024) {
        int idx = base + t;
        int v = (idx < Nn) ? d_deg[idx] : 0;
        int incl = v;
#pragma unroll
        for (int off = 1; off < 32; off <<= 1) {
            int n = __shfl_up_sync(0xFFFFFFFFu, incl, off);
            if (lane >= off) incl += n;
        }
        if (lane == 31) warpsum[w] = incl;
        __syncthreads();
        if (w == 0) {
            int ws = warpsum[lane];
            int wincl = ws;
#pragma unroll
            for (int off = 1; off < 32; off <<= 1) {
                int n = __shfl_up_sync(0xFFFFFFFFu, wincl, off);
                if (lane >= off) wincl += n;
            }
            warpsum[lane] = wincl;
        }
        __syncthreads();
        int offset = s_carry + ((w > 0) ? warpsum[w - 1] : 0);
        int excl = offset + incl - v;
        if (idx < Nn) {
            d_rowstart[idx] = excl;
            d_csrc[excl]    = idx;       // self loop first
            d_cursor[idx]   = excl + 1;
        }
        __syncthreads();
        if (t == 1023) s_carry = offset + incl;
        __syncthreads();
    }
}

// scatter real edges into CSR order
__global__ void __launch_bounds__(256) k_fill(const int* __restrict__ ei) {
    int i = blockIdx.x * blockDim.x + threadIdx.x;
    if (i >= Ee) return;
    int src = __ldg(&ei[i]);
    int dst = __ldg(&ei[Ee + i]);
    int pos = atomicAdd(&d_cursor[dst], 1);
    d_csrc[pos] = src;
}

// xl|xr = x @ [Wl|Wr]: register-tiled SGEMM.
// Block = 32 nodes x 64 cols, 128 threads, each thread 4x4 outputs.
// Weights (128x64, 32KB) + x tile (32x128, 16KB) fully smem-resident.
__global__ void __launch_bounds__(128) k_transform(
    const float* __restrict__ x,
    const float* __restrict__ Wl,
    const float* __restrict__ Wr)
{
    __shared__ float sW[Ff * 64];   // [k][c]
    __shared__ float sx[32 * Ff];   // [n][k]

    int t = threadIdx.x;
    for (int i = t; i < Ff * 64; i += 128) {
        int k = i >> 6, c = i & 63;
        sW[i] = (c < 32) ? Wl[k * Hh + c] : Wr[k * Hh + (c - 32)];
    }
    int n0 = blockIdx.x * 32;    // 100000 % 32 == 0
    const float4* xg = (const float4*)(x + (size_t)n0 * Ff);
    float4* sxw = (float4*)sx;
    for (int i = t; i < (32 * Ff) / 4; i += 128) sxw[i] = xg[i];
    __syncthreads();

    int tx = t & 15, ty = t >> 4;
    int c0 = tx * 4, nb = ty * 4;
    const float4* sW4 = (const float4*)sW;
    const float4* sx4 = (const float4*)sx;

    float acc[4][4] = {};
#pragma unroll 8
    for (int k4 = 0; k4 < Ff / 4; k4++) {
        float4 w0 = sW4[(k4 * 4 + 0) * 16 + tx];
        float4 w1 = sW4[(k4 * 4 + 1) * 16 + tx];
        float4 w2 = sW4[(k4 * 4 + 2) * 16 + tx];
        float4 w3 = sW4[(k4 * 4 + 3) * 16 + tx];
#pragma unroll
        for (int i = 0; i < 4; i++) {
            float4 xv = sx4[(nb + i) * (Ff / 4) + k4];
            acc[i][0] += xv.x * w0.x + xv.y * w1.x + xv.z * w2.x + xv.w * w3.x;
            acc[i][1] += xv.x * w0.y + xv.y * w1.y + xv.z * w2.y + xv.w * w3.y;
            acc[i][2] += xv.x * w0.z + xv.y * w1.z + xv.z * w2.z + xv.w * w3.z;
            acc[i][3] += xv.x * w0.w + xv.y * w1.w + xv.z * w2.w + xv.w * w3.w;
        }
    }
#pragma unroll
    for (int i = 0; i < 4; i++) {
        int node = n0 + nb + i;
        float4 v = make_float4(acc[i][0], acc[i][1], acc[i][2], acc[i][3]);
        if (c0 < 32) *(float4*)&d_xl[node * Hh + c0] = v;
        else         *(float4*)&d_xr[node * Hh + (c0 - 32)] = v;
    }
}

// Fused GATv2 edge phase: one warp per destination node.
// Online softmax over incoming edges (exact), accumulate alpha*xl in regs,
// then one atomicMax into the per-graph pooled max. Zero edge-output atomics.
__global__ void __launch_bounds__(256) k_node(
    const float* __restrict__ att, const int* __restrict__ batch)
{
    int node = (int)((blockIdx.x * (unsigned)blockDim.x + threadIdx.x) >> 5);
    int lane = threadIdx.x & 31;
    if (node >= Nn) return;

    int beg = d_rowstart[node];
    int end = beg + d_deg[node];
    float xr = d_xr[node * Hh + lane];
    float al = __ldg(&att[lane]);

    float m = -CUDART_INF_F, z = 0.0f, acc = 0.0f;

    for (int j0 = beg; j0 < end; j0 += 32) {
        int myidx = j0 + lane;
        int msrc = (myidx < end) ? d_csrc[myidx] : 0;
        int cnt = min(32, end - j0);
        for (int k = 0; k < cnt; k++) {
            int src = __shfl_sync(0xFFFFFFFFu, msrc, k);
            float v = d_xl[src * Hh + lane];
            float s = v + xr;
            s = (s >= 0.0f) ? s : 0.2f * s;
            s *= al;
#pragma unroll
            for (int off = 16; off; off >>= 1)
                s += __shfl_xor_sync(0xFFFFFFFFu, s, off);
            // online softmax update (m,z replicated across lanes)
            float mnew = fmaxf(m, s);
            float scale = __expf(m - mnew);   // exp(-inf)=0 on first edge
            float p = __expf(s - mnew);
            z   = z * scale + p;
            acc = acc * scale + p * v;
            m = mnew;
        }
    }
    float out = acc / z;
    int bg = __ldg(&batch[node]);
    atomicMax(&d_g[bg * Hh + lane], fenc(out));
}

// h1 = relu((g + bias) @ W1 + b1)
__global__ void __launch_bounds__(1024) k_mlp1(
    const float* __restrict__ W1, const float* __restrict__ b1,
    const float* __restrict__ bias)
{
    __shared__ float sg[Hh];
    int b = blockIdx.x;
    int j = threadIdx.x;
    if (j < Hh) sg[j] = fdec(d_g[b * Hh + j]) + bias[j];
    __syncthreads();
    float acc = b1[j];
#pragma unroll
    for (int k = 0; k < Hh; k++) acc += sg[k] * W1[k * D1 + j];
    d_h1[b * D1 + j] = fmaxf(acc, 0.0f);
}

// h2 = relu(h1 @ W2 + b2); 4 rows per block for W2 reuse
#define R2 4
__global__ void __launch_bounds__(512) k_mlp2(
    const float* __restrict__ W2, const float* __restrict__ b2)
{
    __shared__ float sh[R2 * D1];
    int j = threadIdx.x;
    int rb = blockIdx.x * R2;
    for (int i = j; i < R2 * D1; i += 512) sh[i] = d_h1[rb * D1 + i];
    __syncthreads();

    float acc[R2];
#pragma unroll
    for (int r = 0; r < R2; r++) acc[r] = b2[j];

    const float4* sh4 = (const float4*)sh;
#pragma unroll 4
    for (int k4 = 0; k4 < D1 / 4; k4++) {
        int k = k4 * 4;
        float w0 = W2[(k + 0) * D2 + j];
        float w1 = W2[(k + 1) * D2 + j];
        float w2 = W2[(k + 2) * D2 + j];
        float w3 = W2[(k + 3) * D2 + j];
#pragma unroll
        for (int r = 0; r < R2; r++) {
            float4 s = sh4[r * (D1 / 4) + k4];
            acc[r] += s.x * w0 + s.y * w1 + s.z * w2 + s.w * w3;
        }
    }
#pragma unroll
    for (int r = 0; r < R2; r++) d_h2[(rb + r) * D2 + j] = fmaxf(acc[r], 0.0f);
}

// out = h2 @ W3 + b3
__global__ void __launch_bounds__(128) k_mlp3(
    const float* __restrict__ W3, const float* __restrict__ b3,
    float* __restrict__ out)
{
    int b = blockIdx.x;
    int w = threadIdx.x >> 5;
    int lane = threadIdx.x & 31;
    float acc = 0.0f;
#pragma unroll
    for (int k = lane; k < D2; k += 32)
        acc += d_h2[b * D2 + k] * W3[k * D3 + w];
#pragma unroll
    for (int off = 16; off; off >>= 1) acc += __shfl_xor_sync(0xFFFFFFFFu, acc, off);
    if (lane == 0) out[b * D3 + w] = acc + b3[w];
}

// ---------------- launch -----------------------------------------------------
extern "C" void kernel_launch(void* const* d_in, const int* in_sizes, int n_in,
                              void* d_out, int out_size)
{
    const float* x    = (const float*)d_in[0];
    const int*   ei   = (const int*)  d_in[1];
    const int*   batch= (const int*)  d_in[2];
    const float* Wl   = (const float*)d_in[3];
    const float* Wr   = (const float*)d_in[4];
    const float* att  = (const float*)d_in[5];
    const float* bias = (const float*)d_in[6];
    const float* W1   = (const float*)d_in[7];
    const float* b1   = (const float*)d_in[8];
    const float* W2   = (const float*)d_in[9];
    const float* b2   = (const float*)d_in[10];
    const float* W3   = (const float*)d_in[11];
    const float* b3   = (const float*)d_in[12];
    float* out = (float*)d_out;

    k_init<<<(Nn + 255) / 256, 256>>>();
    k_count<<<(Ee + 255) / 256, 256>>>(ei);
    k_scan<<<1, 1024>>>();
    k_fill<<<(Ee + 255) / 256, 256>>>(ei);
    k_transform<<<Nn / 32, 128>>>(x, Wl, Wr);
    k_node<<<(Nn * 32 + 255) / 256, 256>>>(att, batch);
    k_mlp1<<<Bb, D1>>>(W1, b1, bias);
    k_mlp2<<<Bb / R2, 512>>>(W2, b2);
    k_mlp3<<<Bb, 128>>>(W3, b3, out);
}

// round 6
// speedup vs baseline: 2.3524x; 1.1738x over previous
#include <cuda_runtime.h>
#include <math_constants.h>

// Problem constants (fixed by the reference)
#define Nn 100000
#define Ee 3200000
#define EN (Ee + Nn)      // edges + self loops
#define Hh 32
#define Ff 128
#define Bb 256
#define D1 1024
#define D2 512
#define D3 4
#define NB 98             // scan blocks: ceil(100000/1024)

// ---------------- scratch (static device globals; no allocation) -----------
__device__ float        d_xl[Nn * Hh];       // x @ Wl
__device__ float        d_xr[Nn * Hh];       // x @ Wr
__device__ int          d_deg[Nn];           // in-degree incl. self loop
__device__ int          d_rowstart[Nn];      // CSR row offsets
__device__ int          d_cursor[Nn];        // fill cursors
__device__ int          d_csrc[EN];          // CSR source indices (by dst)
__device__ float        d_e[EN];             // per-edge scores (CSR order)
__device__ int          d_bsum[NB];          // scan partials
__device__ int          d_bpre[NB];          // scan block prefixes
__device__ unsigned int d_g[Bb * Hh];        // pooled max per graph (encoded)
__device__ float        d_h1[Bb * D1];
__device__ float        d_h2[Bb * D2];

// order-preserving float<->unsigned encoding for atomicMax on floats
__device__ __forceinline__ unsigned int fenc(float f) {
    unsigned int u = __float_as_uint(f);
    return u ^ ((unsigned int)((int)u >> 31) | 0x80000000u);
}
__device__ __forceinline__ float fdec(unsigned int e) {
    unsigned int mask = ((int)e < 0) ? 0x80000000u : 0xFFFFFFFFu;
    return __uint_as_float(e ^ mask);
}
#define ENC_NEG_INF 0x007FFFFFu

__device__ __forceinline__ int wscan_incl(int v, int lane) {
#pragma unroll
    for (int off = 1; off < 32; off <<= 1) {
        int n = __shfl_up_sync(0xFFFFFFFFu, v, off);
        if (lane >= off) v += n;
    }
    return v;
}

// ---------------- kernels ---------------------------------------------------

// init: deg=1 (self loop), pooled max = -inf
__global__ void k_init() {
    int i = blockIdx.x * blockDim.x + threadIdx.x;
    if (i < Nn) d_deg[i] = 1;
    if (i < Bb * Hh) d_g[i] = ENC_NEG_INF;
}

// degree histogram: 4 edges per thread (int4), fire-and-forget RED atomics
__global__ void __launch_bounds__(256) k_count(const int* __restrict__ ei) {
    int i4 = blockIdx.x * blockDim.x + threadIdx.x;   // 0 .. Ee/4
    if (i4 >= Ee / 4) return;
    int4 d = ((const int4*)(ei + Ee))[i4];
    atomicAdd(&d_deg[d.x], 1);
    atomicAdd(&d_deg[d.y], 1);
    atomicAdd(&d_deg[d.z], 1);
    atomicAdd(&d_deg[d.w], 1);
}

// scan phase 1: per-block sums of d_deg
__global__ void __launch_bounds__(1024) k_bsum() {
    __shared__ int sred[32];
    int t = threadIdx.x, lane = t & 31, w = t >> 5;
    int idx = blockIdx.x * 1024 + t;
    int v = (idx < Nn) ? d_deg[idx] : 0;
#pragma unroll
    for (int off = 16; off; off >>= 1) v += __shfl_xor_sync(0xFFFFFFFFu, v, off);
    if (lane == 0) sred[w] = v;
    __syncthreads();
    if (w == 0) {
        int s = sred[lane];
#pragma unroll
        for (int off = 16; off; off >>= 1) s += __shfl_xor_sync(0xFFFFFFFFu, s, off);
        if (lane == 0) d_bsum[blockIdx.x] = s;
    }
}

// scan phase 2: exclusive scan of NB block sums (1 small block)
__global__ void __launch_bounds__(128) k_bscan() {
    __shared__ int wsum[4];
    int t = threadIdx.x, lane = t & 31, w = t >> 5;
    int v = (t < NB) ? d_bsum[t] : 0;
    int incl = wscan_incl(v, lane);
    if (lane == 31) wsum[w] = incl;
    __syncthreads();
    if (t == 0) {
        int run = 0;
#pragma unroll
        for (int i = 0; i < 4; i++) { int tmp = wsum[i]; wsum[i] = run; run += tmp; }
    }
    __syncthreads();
    if (t < NB) d_bpre[t] = wsum[w] + incl - v;
}

// scan phase 3: intra-block scan + block prefix -> rowstart, self-loop, cursor
__global__ void __launch_bounds__(1024) k_scatter() {
    __shared__ int wsum[32];
    int t = threadIdx.x, lane = t & 31, w = t >> 5;
    int idx = blockIdx.x * 1024 + t;
    int v = (idx < Nn) ? d_deg[idx] : 0;
    int incl = wscan_incl(v, lane);
    if (lane == 31) wsum[w] = incl;
    __syncthreads();
    if (w == 0) wsum[lane] = wscan_incl(wsum[lane], lane);
    __syncthreads();
    int off = d_bpre[blockIdx.x] + ((w > 0) ? wsum[w - 1] : 0);
    int excl = off + incl - v;
    if (idx < Nn) {
        d_rowstart[idx] = excl;
        d_csrc[excl]    = idx;       // self loop first
        d_cursor[idx]   = excl + 1;
    }
}

// scatter real edges into CSR order: 4 edges per thread, 4 atomics in flight
__global__ void __launch_bounds__(256) k_fill(const int* __restrict__ ei) {
    int i4 = blockIdx.x * blockDim.x + threadIdx.x;
    if (i4 >= Ee / 4) return;
    int4 s = ((const int4*)ei)[i4];
    int4 d = ((const int4*)(ei + Ee))[i4];
    int p0 = atomicAdd(&d_cursor[d.x], 1);
    int p1 = atomicAdd(&d_cursor[d.y], 1);
    int p2 = atomicAdd(&d_cursor[d.z], 1);
    int p3 = atomicAdd(&d_cursor[d.w], 1);
    d_csrc[p0] = s.x;
    d_csrc[p1] = s.y;
    d_csrc[p2] = s.z;
    d_csrc[p3] = s.w;
}

// xl|xr = x @ [Wl|Wr]: register-tiled SGEMM (32 nodes x 64 cols per block)
__global__ void __launch_bounds__(128) k_transform(
    const float* __restrict__ x,
    const float* __restrict__ Wl,
    const float* __restrict__ Wr)
{
    __shared__ float sW[Ff * 64];   // [k][c]
    __shared__ float sx[32 * Ff];   // [n][k]

    int t = threadIdx.x;
    for (int i = t; i < Ff * 64; i += 128) {
        int k = i >> 6, c = i & 63;
        sW[i] = (c < 32) ? Wl[k * Hh + c] : Wr[k * Hh + (c - 32)];
    }
    int n0 = blockIdx.x * 32;
    const float4* xg = (const float4*)(x + (size_t)n0 * Ff);
    float4* sxw = (float4*)sx;
    for (int i = t; i < (32 * Ff) / 4; i += 128) sxw[i] = xg[i];
    __syncthreads();

    int tx = t & 15, ty = t >> 4;
    int c0 = tx * 4, nb = ty * 4;
    const float4* sW4 = (const float4*)sW;
    const float4* sx4 = (const float4*)sx;

    float acc[4][4] = {};
#pragma unroll 8
    for (int k4 = 0; k4 < Ff / 4; k4++) {
        float4 w0 = sW4[(k4 * 4 + 0) * 16 + tx];
        float4 w1 = sW4[(k4 * 4 + 1) * 16 + tx];
        float4 w2 = sW4[(k4 * 4 + 2) * 16 + tx];
        float4 w3 = sW4[(k4 * 4 + 3) * 16 + tx];
#pragma unroll
        for (int i = 0; i < 4; i++) {
            float4 xv = sx4[(nb + i) * (Ff / 4) + k4];
            acc[i][0] += xv.x * w0.x + xv.y * w1.x + xv.z * w2.x + xv.w * w3.x;
            acc[i][1] += xv.x * w0.y + xv.y * w1.y + xv.z * w2.y + xv.w * w3.y;
            acc[i][2] += xv.x * w0.z + xv.y * w1.z + xv.z * w2.z + xv.w * w3.z;
            acc[i][3] += xv.x * w0.w + xv.y * w1.w + xv.z * w2.w + xv.w * w3.w;
        }
    }
#pragma unroll
    for (int i = 0; i < 4; i++) {
        int node = n0 + nb + i;
        float4 v = make_float4(acc[i][0], acc[i][1], acc[i][2], acc[i][3]);
        if (c0 < 32) *(float4*)&d_xl[node * Hh + c0] = v;
        else         *(float4*)&d_xr[node * Hh + (c0 - 32)] = v;
    }
}

// Fused GATv2 edge phase: one warp per destination node.
// Loop 1: scores -> d_e (CSR-order, coalesced), running max (no exp chain).
// Loop 2: lane-parallel exp + sum + register aggregation.
__global__ void __launch_bounds__(256) k_node(
    const float* __restrict__ att, const int* __restrict__ batch)
{
    int node = (int)((blockIdx.x * (unsigned)blockDim.x + threadIdx.x) >> 5);
    int lane = threadIdx.x & 31;
    if (node >= Nn) return;

    int beg = d_rowstart[node];
    int end = beg + d_deg[node];
    float xr = d_xr[node * Hh + lane];
    float al = __ldg(&att[lane]);

    // ---- loop 1: scores ----
    float m = -CUDART_INF_F;
    for (int j0 = beg; j0 < end; j0 += 32) {
        int myidx = j0 + lane;
        int msrc = (myidx < end) ? d_csrc[myidx] : 0;
        int cnt = min(32, end - j0);
        float e_keep = 0.0f;
#pragma unroll 2
        for (int k = 0; k < cnt; k++) {
            int src = __shfl_sync(0xFFFFFFFFu, msrc, k);
            float v = d_xl[src * Hh + lane];
            float s = v + xr;
            s = fmaxf(s, 0.2f * s);          // leaky_relu, slope 0.2
            s *= al;
#pragma unroll
            for (int off = 16; off; off >>= 1)
                s += __shfl_xor_sync(0xFFFFFFFFu, s, off);
            if (lane == k) e_keep = s;
            m = fmaxf(m, s);
        }
        if (myidx < end) d_e[myidx] = e_keep;   // coalesced store
    }
    // m is replicated across lanes (s was fully reduced)

    // ---- loop 2: exp + sum + aggregate ----
    float z = 0.0f, acc = 0.0f;
    for (int j0 = beg; j0 < end; j0 += 32) {
        int myidx = j0 + lane;
        bool act = myidx < end;
        float p = act ? __expf(d_e[myidx] - m) : 0.0f;
        int msrc = act ? d_csrc[myidx] : 0;
        z += p;
        int cnt = min(32, end - j0);
#pragma unroll 2
        for (int k = 0; k < cnt; k++) {
            float pk = __shfl_sync(0xFFFFFFFFu, p, k);
            int   sk = __shfl_sync(0xFFFFFFFFu, msrc, k);
            acc += pk * d_xl[sk * Hh + lane];
        }
    }
#pragma unroll
    for (int off = 16; off; off >>= 1) z += __shfl_xor_sync(0xFFFFFFFFu, z, off);

    float out = acc / z;
    int bg = __ldg(&batch[node]);
    atomicMax(&d_g[bg * Hh + lane], fenc(out));
}

// h1 = relu((g + bias) @ W1 + b1)
__global__ void __launch_bounds__(1024) k_mlp1(
    const float* __restrict__ W1, const float* __restrict__ b1,
    const float* __restrict__ bias)
{
    __shared__ float sg[Hh];
    int b = blockIdx.x;
    int j = threadIdx.x;
    if (j < Hh) sg[j] = fdec(d_g[b * Hh + j]) + bias[j];
    __syncthreads();
    float acc = b1[j];
#pragma unroll
    for (int k = 0; k < Hh; k++) acc += sg[k] * W1[k * D1 + j];
    d_h1[b * D1 + j] = fmaxf(acc, 0.0f);
}

// h2 = relu(h1 @ W2 + b2); 4 rows per block for W2 reuse
#define R2 4
__global__ void __launch_bounds__(512) k_mlp2(
    const float* __restrict__ W2, const float* __restrict__ b2)
{
    __shared__ float sh[R2 * D1];
    int j = threadIdx.x;
    int rb = blockIdx.x * R2;
    for (int i = j; i < R2 * D1; i += 512) sh[i] = d_h1[rb * D1 + i];
    __syncthreads();

    float acc[R2];
#pragma unroll
    for (int r = 0; r < R2; r++) acc[r] = b2[j];

    const float4* sh4 = (const float4*)sh;
#pragma unroll 4
    for (int k4 = 0; k4 < D1 / 4; k4++) {
        int k = k4 * 4;
        float w0 = W2[(k + 0) * D2 + j];
        float w1 = W2[(k + 1) * D2 + j];
        float w2 = W2[(k + 2) * D2 + j];
        float w3 = W2[(k + 3) * D2 + j];
#pragma unroll
        for (int r = 0; r < R2; r++) {
            float4 s = sh4[r * (D1 / 4) + k4];
            acc[r] += s.x * w0 + s.y * w1 + s.z * w2 + s.w * w3;
        }
    }
#pragma unroll
    for (int r = 0; r < R2; r++) d_h2[(rb + r) * D2 + j] = fmaxf(acc[r], 0.0f);
}

// out = h2 @ W3 + b3
__global__ void __launch_bounds__(128) k_mlp3(
    const float* __restrict__ W3, const float* __restrict__ b3,
    float* __restrict__ out)
{
    int b = blockIdx.x;
    int w = threadIdx.x >> 5;
    int lane = threadIdx.x & 31;
    float acc = 0.0f;
#pragma unroll
    for (int k = lane; k < D2; k += 32)
        acc += d_h2[b * D2 + k] * W3[k * D3 + w];
#pragma unroll
    for (int off = 16; off; off >>= 1) acc += __shfl_xor_sync(0xFFFFFFFFu, acc, off);
    if (lane == 0) out[b * D3 + w] = acc + b3[w];
}

// ---------------- launch -----------------------------------------------------
extern "C" void kernel_launch(void* const* d_in, const int* in_sizes, int n_in,
                              void* d_out, int out_size)
{
    const float* x    = (const float*)d_in[0];
    const int*   ei   = (const int*)  d_in[1];
    const int*   batch= (const int*)  d_in[2];
    const float* Wl   = (const float*)d_in[3];
    const float* Wr   = (const float*)d_in[4];
    const float* att  = (const float*)d_in[5];
    const float* bias = (const float*)d_in[6];
    const float* W1   = (const float*)d_in[7];
    const float* b1   = (const float*)d_in[8];
    const float* W2   = (const float*)d_in[9];
    const float* b2   = (const float*)d_in[10];
    const float* W3   = (const float*)d_in[11];
    const float* b3   = (const float*)d_in[12];
    float* out = (float*)d_out;

    k_init<<<(Nn + 255) / 256, 256>>>();
    k_count<<<(Ee / 4 + 255) / 256, 256>>>(ei);
    k_bsum<<<NB, 1024>>>();
    k_bscan<<<1, 128>>>();
    k_scatter<<<NB, 1024>>>();
    k_fill<<<(Ee / 4 + 255) / 256, 256>>>(ei);
    k_transform<<<Nn / 32, 128>>>(x, Wl, Wr);
    k_node<<<(Nn * 32 + 255) / 256, 256>>>(att, batch);
    k_mlp1<<<Bb, D1>>>(W1, b1, bias);
    k_mlp2<<<Bb / R2, 512>>>(W2, b2);
    k_mlp3<<<Bb, 128>>>(W3, b3, out);
}

// round 7
// speedup vs baseline: 2.5969x; 1.1040x over previous
#include <cuda_runtime.h>
#include <math_constants.h>

// Problem constants (fixed by the reference)
#define Nn 100000
#define Ee 3200000
#define EN (Ee + Nn)      // edges + self loops
#define Hh 32
#define Ff 128
#define Bb 256
#define D1 1024
#define D2 512
#define D3 4
#define NB 98             // scan blocks: ceil(100000/1024)

// ---------------- scratch (static device globals; no allocation) -----------
__device__ float        d_xl[Nn * Hh];       // x @ Wl
__device__ float        d_xr[Nn * Hh];       // x @ Wr
__device__ int          d_deg[Nn];           // in-degree incl. self loop
__device__ int          d_rowstart[Nn];      // CSR row offsets
__device__ int          d_cursor[Nn];        // fill cursors
__device__ int          d_csrc[EN];          // CSR source indices (by dst)
__device__ int          d_bsum[NB];          // scan partials
__device__ int          d_bpre[NB];          // scan block prefixes
__device__ unsigned int d_g[Bb * Hh];        // pooled max per graph (encoded)
__device__ float        d_h1[Bb * D1];
__device__ float        d_h2[Bb * D2];

// order-preserving float<->unsigned encoding for atomicMax on floats
__device__ __forceinline__ unsigned int fenc(float f) {
    unsigned int u = __float_as_uint(f);
    return u ^ ((unsigned int)((int)u >> 31) | 0x80000000u);
}
__device__ __forceinline__ float fdec(unsigned int e) {
    unsigned int mask = ((int)e < 0) ? 0x80000000u : 0xFFFFFFFFu;
    return __uint_as_float(e ^ mask);
}
#define ENC_NEG_INF 0x007FFFFFu

__device__ __forceinline__ int wscan_incl(int v, int lane) {
#pragma unroll
    for (int off = 1; off < 32; off <<= 1) {
        int n = __shfl_up_sync(0xFFFFFFFFu, v, off);
        if (lane >= off) v += n;
    }
    return v;
}

// ---------------- kernels ---------------------------------------------------

// init: deg=1 (self loop), pooled max = -inf
__global__ void k_init() {
    int i = blockIdx.x * blockDim.x + threadIdx.x;
    if (i < Nn) d_deg[i] = 1;
    if (i < Bb * Hh) d_g[i] = ENC_NEG_INF;
}

// degree histogram: 8 edges per thread (2x int4), fire-and-forget RED atomics
__global__ void __launch_bounds__(256) k_count(const int* __restrict__ ei) {
    int i8 = blockIdx.x * blockDim.x + threadIdx.x;   // 0 .. Ee/8
    if (i8 >= Ee / 8) return;
    const int4* d4 = (const int4*)(ei + Ee);
    int4 a = d4[i8 * 2];
    int4 b = d4[i8 * 2 + 1];
    atomicAdd(&d_deg[a.x], 1);
    atomicAdd(&d_deg[a.y], 1);
    atomicAdd(&d_deg[a.z], 1);
    atomicAdd(&d_deg[a.w], 1);
    atomicAdd(&d_deg[b.x], 1);
    atomicAdd(&d_deg[b.y], 1);
    atomicAdd(&d_deg[b.z], 1);
    atomicAdd(&d_deg[b.w], 1);
}

// scan phase 1: per-block sums of d_deg
__global__ void __launch_bounds__(1024) k_bsum() {
    __shared__ int sred[32];
    int t = threadIdx.x, lane = t & 31, w = t >> 5;
    int idx = blockIdx.x * 1024 + t;
    int v = (idx < Nn) ? d_deg[idx] : 0;
#pragma unroll
    for (int off = 16; off; off >>= 1) v += __shfl_xor_sync(0xFFFFFFFFu, v, off);
    if (lane == 0) sred[w] = v;
    __syncthreads();
    if (w == 0) {
        int s = sred[lane];
#pragma unroll
        for (int off = 16; off; off >>= 1) s += __shfl_xor_sync(0xFFFFFFFFu, s, off);
        if (lane == 0) d_bsum[blockIdx.x] = s;
    }
}

// scan phase 2: exclusive scan of NB block sums (1 small block)
__global__ void __launch_bounds__(128) k_bscan() {
    __shared__ int wsum[4];
    int t = threadIdx.x, lane = t & 31, w = t >> 5;
    int v = (t < NB) ? d_bsum[t] : 0;
    int incl = wscan_incl(v, lane);
    if (lane == 31) wsum[w] = incl;
    __syncthreads();
    if (t == 0) {
        int run = 0;
#pragma unroll
        for (int i = 0; i < 4; i++) { int tmp = wsum[i]; wsum[i] = run; run += tmp; }
    }
    __syncthreads();
    if (t < NB) d_bpre[t] = wsum[w] + incl - v;
}

// scan phase 3: intra-block scan + block prefix -> rowstart, self-loop, cursor
__global__ void __launch_bounds__(1024) k_scatter() {
    __shared__ int wsum[32];
    int t = threadIdx.x, lane = t & 31, w = t >> 5;
    int idx = blockIdx.x * 1024 + t;
    int v = (idx < Nn) ? d_deg[idx] : 0;
    int incl = wscan_incl(v, lane);
    if (lane == 31) wsum[w] = incl;
    __syncthreads();
    if (w == 0) wsum[lane] = wscan_incl(wsum[lane], lane);
    __syncthreads();
    int off = d_bpre[blockIdx.x] + ((w > 0) ? wsum[w - 1] : 0);
    int excl = off + incl - v;
    if (idx < Nn) {
        d_rowstart[idx] = excl;
        d_csrc[excl]    = idx;       // self loop first
        d_cursor[idx]   = excl + 1;
    }
}

// scatter real edges into CSR order: 8 edges per thread, 8 atomics in flight
__global__ void __launch_bounds__(256) k_fill(const int* __restrict__ ei) {
    int i8 = blockIdx.x * blockDim.x + threadIdx.x;
    if (i8 >= Ee / 8) return;
    const int4* s4 = (const int4*)ei;
    const int4* d4 = (const int4*)(ei + Ee);
    int4 sa = s4[i8 * 2], sb = s4[i8 * 2 + 1];
    int4 da = d4[i8 * 2], db = d4[i8 * 2 + 1];
    int p0 = atomicAdd(&d_cursor[da.x], 1);
    int p1 = atomicAdd(&d_cursor[da.y], 1);
    int p2 = atomicAdd(&d_cursor[da.z], 1);
    int p3 = atomicAdd(&d_cursor[da.w], 1);
    int p4 = atomicAdd(&d_cursor[db.x], 1);
    int p5 = atomicAdd(&d_cursor[db.y], 1);
    int p6 = atomicAdd(&d_cursor[db.z], 1);
    int p7 = atomicAdd(&d_cursor[db.w], 1);
    d_csrc[p0] = sa.x;
    d_csrc[p1] = sa.y;
    d_csrc[p2] = sa.z;
    d_csrc[p3] = sa.w;
    d_csrc[p4] = sb.x;
    d_csrc[p5] = sb.y;
    d_csrc[p6] = sb.z;
    d_csrc[p7] = sb.w;
}

// xl|xr = x @ [Wl|Wr]: register-tiled SGEMM (32 nodes x 64 cols per block)
__global__ void __launch_bounds__(128) k_transform(
    const float* __restrict__ x,
    const float* __restrict__ Wl,
    const float* __restrict__ Wr)
{
    __shared__ float sW[Ff * 64];   // [k][c]
    __shared__ float sx[32 * Ff];   // [n][k]

    int t = threadIdx.x;
    for (int i = t; i < Ff * 64; i += 128) {
        int k = i >> 6, c = i & 63;
        sW[i] = (c < 32) ? Wl[k * Hh + c] : Wr[k * Hh + (c - 32)];
    }
    int n0 = blockIdx.x * 32;
    const float4* xg = (const float4*)(x + (size_t)n0 * Ff);
    float4* sxw = (float4*)sx;
    for (int i = t; i < (32 * Ff) / 4; i += 128) sxw[i] = xg[i];
    __syncthreads();

    int tx = t & 15, ty = t >> 4;
    int c0 = tx * 4, nb = ty * 4;
    const float4* sW4 = (const float4*)sW;
    const float4* sx4 = (const float4*)sx;

    float acc[4][4] = {};
#pragma unroll 8
    for (int k4 = 0; k4 < Ff / 4; k4++) {
        float4 w0 = sW4[(k4 * 4 + 0) * 16 + tx];
        float4 w1 = sW4[(k4 * 4 + 1) * 16 + tx];
        float4 w2 = sW4[(k4 * 4 + 2) * 16 + tx];
        float4 w3 = sW4[(k4 * 4 + 3) * 16 + tx];
#pragma unroll
        for (int i = 0; i < 4; i++) {
            float4 xv = sx4[(nb + i) * (Ff / 4) + k4];
            acc[i][0] += xv.x * w0.x + xv.y * w1.x + xv.z * w2.x + xv.w * w3.x;
            acc[i][1] += xv.x * w0.y + xv.y * w1.y + xv.z * w2.y + xv.w * w3.y;
            acc[i][2] += xv.x * w0.z + xv.y * w1.z + xv.z * w2.z + xv.w * w3.z;
            acc[i][3] += xv.x * w0.w + xv.y * w1.w + xv.z * w2.w + xv.w * w3.w;
        }
    }
#pragma unroll
    for (int i = 0; i < 4; i++) {
        int node = n0 + nb + i;
        float4 v = make_float4(acc[i][0], acc[i][1], acc[i][2], acc[i][3]);
        if (c0 < 32) *(float4*)&d_xl[node * Hh + c0] = v;
        else         *(float4*)&d_xr[node * Hh + (c0 - 32)] = v;
    }
}

// Fused GATv2 edge phase v3: one warp per destination node, tile-transposed.
// Per 32-edge tile: stage xl[src] rows into smem (coalesced), each LANE owns
// one edge and computes its score lane-parallel (no per-edge shuffles), then
// tile-level online softmax + aggregation reusing the same smem tile.
__global__ void __launch_bounds__(256) k_node(
    const float* __restrict__ att, const int* __restrict__ batch)
{
    __shared__ float tile[8][32][33];   // [warp][edge r][h], padded
    __shared__ float sxr[8][32];        // xr row per warp's node
    __shared__ float satt[32];

    int t = threadIdx.x;
    int lane = t & 31;
    int w = t >> 5;
    if (t < 32) satt[t] = __ldg(&att[t]);
    __syncthreads();

    int node = (int)((blockIdx.x * 8u) + w);
    if (node >= Nn) return;

    int beg = d_rowstart[node];
    int end = beg + d_deg[node];
    sxr[w][lane] = d_xr[node * Hh + lane];
    __syncwarp();

    float m = -CUDART_INF_F, z = 0.0f, acc = 0.0f;

    for (int j0 = beg; j0 < end; j0 += 32) {
        int myidx = j0 + lane;
        int msrc = (myidx < end) ? d_csrc[myidx] : 0;
        int cnt = min(32, end - j0);

        // stage: gather cnt source rows into the tile (coalesced, conflict-free)
#pragma unroll 4
        for (int r = 0; r < cnt; r++) {
            int src = __shfl_sync(0xFFFFFFFFu, msrc, r);
            tile[w][r][lane] = d_xl[src * Hh + lane];
        }
        __syncwarp();

        // score: lane = edge, fully unrolled h loop, no cross-lane deps
        float s = -CUDART_INF_F;
        if (lane < cnt) {
            float sc = 0.0f;
            const float* row = &tile[w][lane][0];
#pragma unroll
            for (int h = 0; h < 32; h++) {
                float v = row[h];
                float u = v + sxr[w][h];
                u = fmaxf(u, 0.2f * u);       // leaky_relu slope 0.2
                sc += u * satt[h];
            }
            s = sc;
        }

        // tile max + online rescale
        float mt = s;
#pragma unroll
        for (int off = 16; off; off >>= 1)
            mt = fmaxf(mt, __shfl_xor_sync(0xFFFFFFFFu, mt, off));
        float mnew = fmaxf(m, mt);
        float scale = __expf(m - mnew);       // first tile: exp(-inf)=0
        float p = (lane < cnt) ? __expf(s - mnew) : 0.0f;

        float ps = p;
#pragma unroll
        for (int off = 16; off; off >>= 1)
            ps += __shfl_xor_sync(0xFFFFFFFFu, ps, off);
        z = z * scale + ps;

        // aggregate: acc[h=lane] = acc*scale + sum_r p_r * tile[r][lane]
        acc *= scale;
#pragma unroll 4
        for (int r = 0; r < cnt; r++) {
            float pr = __shfl_sync(0xFFFFFFFFu, p, r);
            acc += pr * tile[w][r][lane];
        }
        m = mnew;
        __syncwarp();   // protect tile before next stage
    }

    float out = acc / z;
    int bg = __ldg(&batch[node]);
    atomicMax(&d_g[bg * Hh + lane], fenc(out));
}

// h1 = relu((g + bias) @ W1 + b1)
__global__ void __launch_bounds__(1024) k_mlp1(
    const float* __restrict__ W1, const float* __restrict__ b1,
    const float* __restrict__ bias)
{
    __shared__ float sg[Hh];
    int b = blockIdx.x;
    int j = threadIdx.x;
    if (j < Hh) sg[j] = fdec(d_g[b * Hh + j]) + bias[j];
    __syncthreads();
    float acc = b1[j];
#pragma unroll
    for (int k = 0; k < Hh; k++) acc += sg[k] * W1[k * D1 + j];
    d_h1[b * D1 + j] = fmaxf(acc, 0.0f);
}

// h2 = relu(h1 @ W2 + b2); 4 rows per block for W2 reuse
#define R2 4
__global__ void __launch_bounds__(512) k_mlp2(
    const float* __restrict__ W2, const float* __restrict__ b2)
{
    __shared__ float sh[R2 * D1];
    int j = threadIdx.x;
    int rb = blockIdx.x * R2;
    for (int i = j; i < R2 * D1; i += 512) sh[i] = d_h1[rb * D1 + i];
    __syncthreads();

    float acc[R2];
#pragma unroll
    for (int r = 0; r < R2; r++) acc[r] = b2[j];

    const float4* sh4 = (const float4*)sh;
#pragma unroll 4
    for (int k4 = 0; k4 < D1 / 4; k4++) {
        int k = k4 * 4;
        float w0 = W2[(k + 0) * D2 + j];
        float w1 = W2[(k + 1) * D2 + j];
        float w2 = W2[(k + 2) * D2 + j];
        float w3 = W2[(k + 3) * D2 + j];
#pragma unroll
        for (int r = 0; r < R2; r++) {
            float4 s = sh4[r * (D1 / 4) + k4];
            acc[r] += s.x * w0 + s.y * w1 + s.z * w2 + s.w * w3;
        }
    }
#pragma unroll
    for (int r = 0; r < R2; r++) d_h2[(rb + r) * D2 + j] = fmaxf(acc[r], 0.0f);
}

// out = h2 @ W3 + b3
__global__ void __launch_bounds__(128) k_mlp3(
    const float* __restrict__ W3, const float* __restrict__ b3,
    float* __restrict__ out)
{
    int b = blockIdx.x;
    int w = threadIdx.x >> 5;
    int lane = threadIdx.x & 31;
    float acc = 0.0f;
#pragma unroll
    for (int k = lane; k < D2; k += 32)
        acc += d_h2[b * D2 + k] * W3[k * D3 + w];
#pragma unroll
    for (int off = 16; off; off >>= 1) acc += __shfl_xor_sync(0xFFFFFFFFu, acc, off);
    if (lane == 0) out[b * D3 + w] = acc + b3[w];
}

// ---------------- launch -----------------------------------------------------
extern "C" void kernel_launch(void* const* d_in, const int* in_sizes, int n_in,
                              void* d_out, int out_size)
{
    const float* x    = (const float*)d_in[0];
    const int*   ei   = (const int*)  d_in[1];
    const int*   batch= (const int*)  d_in[2];
    const float* Wl   = (const float*)d_in[3];
    const float* Wr   = (const float*)d_in[4];
    const float* att  = (const float*)d_in[5];
    const float* bias = (const float*)d_in[6];
    const float* W1   = (const float*)d_in[7];
    const float* b1   = (const float*)d_in[8];
    const float* W2   = (const float*)d_in[9];
    const float* b2   = (const float*)d_in[10];
    const float* W3   = (const float*)d_in[11];
    const float* b3   = (const float*)d_in[12];
    float* out = (float*)d_out;

    k_init<<<(Nn + 255) / 256, 256>>>();
    k_count<<<(Ee / 8 + 255) / 256, 256>>>(ei);
    k_bsum<<<NB, 1024>>>();
    k_bscan<<<1, 128>>>();
    k_scatter<<<NB, 1024>>>();
    k_fill<<<(Ee / 8 + 255) / 256, 256>>>(ei);
    k_transform<<<Nn / 32, 128>>>(x, Wl, Wr);
    k_node<<<(Nn + 7) / 8, 256>>>(att, batch);
    k_mlp1<<<Bb, D1>>>(W1, b1, bias);
    k_mlp2<<<Bb / R2, 512>>>(W2, b2);
    k_mlp3<<<Bb, 128>>>(W3, b3, out);
}

// round 8
// speedup vs baseline: 2.6521x; 1.0212x over previous
#include <cuda_runtime.h>
#include <math_constants.h>

// Problem constants (fixed by the reference)
#define Nn 100000
#define Ee 3200000
#define EN (Ee + Nn)      // edges + self loops
#define Hh 32
#define Ff 128
#define Bb 256
#define D1 1024
#define D2 512
#define D3 4
#define NB 98             // scan blocks: ceil(100000/1024)

// ---------------- scratch (static device globals; no allocation) -----------
__device__ float        d_xl[Nn * Hh];       // x @ Wl
__device__ float        d_xr[Nn * Hh];       // x @ Wr
__device__ int          d_deg[Nn];           // in-degree incl. self loop
__device__ int          d_rowstart[Nn];      // CSR row offsets
__device__ int          d_cursor[Nn];        // fill cursors
__device__ int          d_csrc[EN];          // CSR source indices (by dst)
__device__ int          d_bsum[NB];          // scan partials
__device__ unsigned int d_g[Bb * Hh];        // pooled max per graph (encoded)
__device__ float        d_h1[Bb * D1];
__device__ float        d_h2[Bb * D2];

// order-preserving float<->unsigned encoding for atomicMax on floats
__device__ __forceinline__ unsigned int fenc(float f) {
    unsigned int u = __float_as_uint(f);
    return u ^ ((unsigned int)((int)u >> 31) | 0x80000000u);
}
__device__ __forceinline__ float fdec(unsigned int e) {
    unsigned int mask = ((int)e < 0) ? 0x80000000u : 0xFFFFFFFFu;
    return __uint_as_float(e ^ mask);
}
#define ENC_NEG_INF 0x007FFFFFu

__device__ __forceinline__ int wscan_incl(int v, int lane) {
#pragma unroll
    for (int off = 1; off < 32; off <<= 1) {
        int n = __shfl_up_sync(0xFFFFFFFFu, v, off);
        if (lane >= off) v += n;
    }
    return v;
}

// ---------------- kernels ---------------------------------------------------

// init: deg=1 (self loop), pooled max = -inf
__global__ void k_init() {
    int i = blockIdx.x * blockDim.x + threadIdx.x;
    if (i < Nn) d_deg[i] = 1;
    if (i < Bb * Hh) d_g[i] = ENC_NEG_INF;
}

// degree histogram: 8 edges per thread (2x int4), fire-and-forget RED atomics
__global__ void __launch_bounds__(256) k_count(const int* __restrict__ ei) {
    int i8 = blockIdx.x * blockDim.x + threadIdx.x;   // 0 .. Ee/8
    if (i8 >= Ee / 8) return;
    const int4* d4 = (const int4*)(ei + Ee);
    int4 a = d4[i8 * 2];
    int4 b = d4[i8 * 2 + 1];
    atomicAdd(&d_deg[a.x], 1);
    atomicAdd(&d_deg[a.y], 1);
    atomicAdd(&d_deg[a.z], 1);
    atomicAdd(&d_deg[a.w], 1);
    atomicAdd(&d_deg[b.x], 1);
    atomicAdd(&d_deg[b.y], 1);
    atomicAdd(&d_deg[b.z], 1);
    atomicAdd(&d_deg[b.w], 1);
}

// scan phase 1: per-block sums of d_deg
__global__ void __launch_bounds__(1024) k_bsum() {
    __shared__ int sred[32];
    int t = threadIdx.x, lane = t & 31, w = t >> 5;
    int idx = blockIdx.x * 1024 + t;
    int v = (idx < Nn) ? d_deg[idx] : 0;
#pragma unroll
    for (int off = 16; off; off >>= 1) v += __shfl_xor_sync(0xFFFFFFFFu, v, off);
    if (lane == 0) sred[w] = v;
    __syncthreads();
    if (w == 0) {
        int s = sred[lane];
#pragma unroll
        for (int off = 16; off; off >>= 1) s += __shfl_xor_sync(0xFFFFFFFFu, s, off);
        if (lane == 0) d_bsum[blockIdx.x] = s;
    }
}

// scan phase 2+3 merged: inline block-prefix over d_bsum, intra-block scan,
// then rowstart/self-loop/cursor.
__global__ void __launch_bounds__(1024) k_scatter() {
    __shared__ int wsum[32];
    __shared__ int sblk[NB];
    __shared__ int s_pre;
    int t = threadIdx.x, lane = t & 31, w = t >> 5;
    int idx = blockIdx.x * 1024 + t;

    if (t < NB) sblk[t] = d_bsum[t];

    int v = (idx < Nn) ? d_deg[idx] : 0;
    int incl = wscan_incl(v, lane);
    if (lane == 31) wsum[w] = incl;
    __syncthreads();
    if (w == 0) {
        // prefix of preceding block sums
        int a = 0;
        for (int c = lane; c < NB; c += 32)
            if (c < blockIdx.x) a += sblk[c];
#pragma unroll
        for (int off = 16; off; off >>= 1) a += __shfl_xor_sync(0xFFFFFFFFu, a, off);
        if (lane == 0) s_pre = a;
        wsum[lane] = wscan_incl(wsum[lane], lane);
    }
    __syncthreads();
    int off = s_pre + ((w > 0) ? wsum[w - 1] : 0);
    int excl = off + incl - v;
    if (idx < Nn) {
        d_rowstart[idx] = excl;
        d_csrc[excl]    = idx;       // self loop first
        d_cursor[idx]   = excl + 1;
    }
}

// scatter real edges into CSR order: 8 edges per thread, 8 atomics in flight
__global__ void __launch_bounds__(256) k_fill(const int* __restrict__ ei) {
    int i8 = blockIdx.x * blockDim.x + threadIdx.x;
    if (i8 >= Ee / 8) return;
    const int4* s4 = (const int4*)ei;
    const int4* d4 = (const int4*)(ei + Ee);
    int4 sa = s4[i8 * 2], sb = s4[i8 * 2 + 1];
    int4 da = d4[i8 * 2], db = d4[i8 * 2 + 1];
    int p0 = atomicAdd(&d_cursor[da.x], 1);
    int p1 = atomicAdd(&d_cursor[da.y], 1);
    int p2 = atomicAdd(&d_cursor[da.z], 1);
    int p3 = atomicAdd(&d_cursor[da.w], 1);
    int p4 = atomicAdd(&d_cursor[db.x], 1);
    int p5 = atomicAdd(&d_cursor[db.y], 1);
    int p6 = atomicAdd(&d_cursor[db.z], 1);
    int p7 = atomicAdd(&d_cursor[db.w], 1);
    d_csrc[p0] = sa.x;
    d_csrc[p1] = sa.y;
    d_csrc[p2] = sa.z;
    d_csrc[p3] = sa.w;
    d_csrc[p4] = sb.x;
    d_csrc[p5] = sb.y;
    d_csrc[p6] = sb.z;
    d_csrc[p7] = sb.w;
}

// xl|xr = x @ [Wl|Wr]: register-tiled SGEMM (32 nodes x 64 cols per block)
__global__ void __launch_bounds__(128) k_transform(
    const float* __restrict__ x,
    const float* __restrict__ Wl,
    const float* __restrict__ Wr)
{
    __shared__ float sW[Ff * 64];   // [k][c]
    __shared__ float sx[32 * Ff];   // [n][k]

    int t = threadIdx.x;
    for (int i = t; i < Ff * 64; i += 128) {
        int k = i >> 6, c = i & 63;
        sW[i] = (c < 32) ? Wl[k * Hh + c] : Wr[k * Hh + (c - 32)];
    }
    int n0 = blockIdx.x * 32;
    const float4* xg = (const float4*)(x + (size_t)n0 * Ff);
    float4* sxw = (float4*)sx;
    for (int i = t; i < (32 * Ff) / 4; i += 128) sxw[i] = xg[i];
    __syncthreads();

    int tx = t & 15, ty = t >> 4;
    int c0 = tx * 4, nb = ty * 4;
    const float4* sW4 = (const float4*)sW;
    const float4* sx4 = (const float4*)sx;

    float acc[4][4] = {};
#pragma unroll 8
    for (int k4 = 0; k4 < Ff / 4; k4++) {
        float4 w0 = sW4[(k4 * 4 + 0) * 16 + tx];
        float4 w1 = sW4[(k4 * 4 + 1) * 16 + tx];
        float4 w2 = sW4[(k4 * 4 + 2) * 16 + tx];
        float4 w3 = sW4[(k4 * 4 + 3) * 16 + tx];
#pragma unroll
        for (int i = 0; i < 4; i++) {
            float4 xv = sx4[(nb + i) * (Ff / 4) + k4];
            acc[i][0] += xv.x * w0.x + xv.y * w1.x + xv.z * w2.x + xv.w * w3.x;
            acc[i][1] += xv.x * w0.y + xv.y * w1.y + xv.z * w2.y + xv.w * w3.y;
            acc[i][2] += xv.x * w0.z + xv.y * w1.z + xv.z * w2.z + xv.w * w3.z;
            acc[i][3] += xv.x * w0.w + xv.y * w1.w + xv.z * w2.w + xv.w * w3.w;
        }
    }
#pragma unroll
    for (int i = 0; i < 4; i++) {
        int node = n0 + nb + i;
        float4 v = make_float4(acc[i][0], acc[i][1], acc[i][2], acc[i][3]);
        if (c0 < 32) *(float4*)&d_xl[node * Hh + c0] = v;
        else         *(float4*)&d_xr[node * Hh + (c0 - 32)] = v;
    }
}

// Fused GATv2 edge phase v4: one warp per destination node, float4 pipeline.
// Stage: 8 lanes per row -> 1 LDG.128 covers 4 rows; tile holds (xl[src]+xr).
// Score: lane = edge, 8x LDS.128. Agg: float4 accumulator over (g,q) split.
// xr un-folded once at the end: out = acc/z - xr.
#define TPITCH 9   // float4 per tile row (36 floats, conflict-free padding)
__global__ void __launch_bounds__(256) k_node(
    const float* __restrict__ att, const int* __restrict__ batch)
{
    __shared__ float4 tile4[8][32 * TPITCH];   // 8 warps x 32 rows x 9 f4 = 36,864B
    __shared__ float  satt[Hh];

    int t = threadIdx.x;
    int lane = t & 31;
    int w = t >> 5;
    if (t < Hh) satt[t] = __ldg(&att[t]);
    // zero this warp's tile (stale-data safety for masked rows)
    float4 z4 = make_float4(0.f, 0.f, 0.f, 0.f);
#pragma unroll
    for (int j = 0; j < TPITCH; j++) tile4[w][lane * TPITCH + j] = z4;
    __syncthreads();

    int node = blockIdx.x * 8 + w;          // Nn % 8 == 0
    int beg = d_rowstart[node];
    int end = beg + d_deg[node];

    int q = lane & 7;           // h-quad (h = 4q..4q+3)
    int g = lane >> 3;          // row subgroup 0..3
    float4 xr4 = *(const float4*)&d_xr[node * Hh + q * 4];

    float m = -CUDART_INF_F, zsum = 0.f;
    float4 acc = z4;

    for (int j0 = beg; j0 < end; j0 += 32) {
        int myidx = j0 + lane;
        int cnt = min(32, end - j0);
        int msrc = (myidx < end) ? d_csrc[myidx] : 0;

        // ---- stage: 8 iterations, 4 rows per LDG.128 ----
#pragma unroll
        for (int i = 0; i < 8; i++) {
            int r = i * 4 + g;
            int src = __shfl_sync(0xFFFFFFFFu, msrc, r);
            if (r < cnt) {
                float4 v = *(const float4*)&d_xl[src * Hh + q * 4];
                v.x += xr4.x; v.y += xr4.y; v.z += xr4.z; v.w += xr4.w;
                tile4[w][r * TPITCH + q] = v;
            }
        }
        __syncwarp();

        // ---- score: lane = edge ----
        float sc = 0.f;
#pragma unroll
        for (int j = 0; j < 8; j++) {
            float4 v = tile4[w][lane * TPITCH + j];
            float4 a = *(const float4*)&satt[j * 4];    // broadcast
            float u;
            u = fmaxf(v.x, 0.2f * v.x); sc += u * a.x;
            u = fmaxf(v.y, 0.2f * v.y); sc += u * a.y;
            u = fmaxf(v.z, 0.2f * v.z); sc += u * a.z;
            u = fmaxf(v.w, 0.2f * v.w); sc += u * a.w;
        }
        float s = (lane < cnt) ? sc : -CUDART_INF_F;

        // ---- tile softmax (online) ----
        float mt = s;
#pragma unroll
        for (int off = 16; off; off >>= 1)
            mt = fmaxf(mt, __shfl_xor_sync(0xFFFFFFFFu, mt, off));
        float mnew = fmaxf(m, mt);
        float scale = __expf(m - mnew);      // first tile: exp(-inf)=0
        float p = __expf(s - mnew);          // masked lanes -> 0
        float ps = p;
#pragma unroll
        for (int off = 16; off; off >>= 1)
            ps += __shfl_xor_sync(0xFFFFFFFFu, ps, off);
        zsum = zsum * scale + ps;
        acc.x *= scale; acc.y *= scale; acc.z *= scale; acc.w *= scale;

        // ---- agg: lane covers (row r = i*4+g, quad q) ----
#pragma unroll
        for (int i = 0; i < 8; i++) {
            int r = i * 4 + g;
            float pr = __shfl_sync(0xFFFFFFFFu, p, r);
            float4 v = tile4[w][r * TPITCH + q];
            acc.x += pr * v.x; acc.y += pr * v.y;
            acc.z += pr * v.z; acc.w += pr * v.w;
        }
        m = mnew;
        __syncwarp();
    }

    // combine across row subgroups (lanes l, l^8, l^16, l^24 share quad q)
#pragma unroll
    for (int off = 8; off <= 16; off <<= 1) {
        acc.x += __shfl_xor_sync(0xFFFFFFFFu, acc.x, off);
        acc.y += __shfl_xor_sync(0xFFFFFFFFu, acc.y, off);
        acc.z += __shfl_xor_sync(0xFFFFFFFFu, acc.z, off);
        acc.w += __shfl_xor_sync(0xFFFFFFFFu, acc.w, off);
    }
    float inv = 1.0f / zsum;
    float compo = (g == 0) ? acc.x : (g == 1) ? acc.y : (g == 2) ? acc.z : acc.w;
    float xrc   = (g == 0) ? xr4.x : (g == 1) ? xr4.y : (g == 2) ? xr4.z : xr4.w;
    float out = compo * inv - xrc;          // un-fold xr
    int h = q * 4 + g;
    int bg = __ldg(&batch[node]);
    atomicMax(&d_g[bg * Hh + h], fenc(out));
}

// h1 = relu((g + bias) @ W1 + b1)
__global__ void __launch_bounds__(1024) k_mlp1(
    const float* __restrict__ W1, const float* __restrict__ b1,
    const float* __restrict__ bias)
{
    __shared__ float sg[Hh];
    int b = blockIdx.x;
    int j = threadIdx.x;
    if (j < Hh) sg[j] = fdec(d_g[b * Hh + j]) + bias[j];
    __syncthreads();
    float acc = b1[j];
#pragma unroll
    for (int k = 0; k < Hh; k++) acc += sg[k] * W1[k * D1 + j];
    d_h1[b * D1 + j] = fmaxf(acc, 0.0f);
}

// h2 = relu(h1 @ W2 + b2); 4 rows per block for W2 reuse
#define R2 4
__global__ void __launch_bounds__(512) k_mlp2(
    const float* __restrict__ W2, const float* __restrict__ b2)
{
    __shared__ float sh[R2 * D1];
    int j = threadIdx.x;
    int rb = blockIdx.x * R2;
    for (int i = j; i < R2 * D1; i += 512) sh[i] = d_h1[rb * D1 + i];
    __syncthreads();

    float acc[R2];
#pragma unroll
    for (int r = 0; r < R2; r++) acc[r] = b2[j];

    const float4* sh4 = (const float4*)sh;
#pragma unroll 4
    for (int k4 = 0; k4 < D1 / 4; k4++) {
        int k = k4 * 4;
        float w0 = W2[(k + 0) * D2 + j];
        float w1 = W2[(k + 1) * D2 + j];
        float w2 = W2[(k + 2) * D2 + j];
        float w3 = W2[(k + 3) * D2 + j];
#pragma unroll
        for (int r = 0; r < R2; r++) {
            float4 s = sh4[r * (D1 / 4) + k4];
            acc[r] += s.x * w0 + s.y * w1 + s.z * w2 + s.w * w3;
        }
    }
#pragma unroll
    for (int r = 0; r < R2; r++) d_h2[(rb + r) * D2 + j] = fmaxf(acc[r], 0.0f);
}

// out = h2 @ W3 + b3
__global__ void __launch_bounds__(128) k_mlp3(
    const float* __restrict__ W3, const float* __restrict__ b3,
    float* __restrict__ out)
{
    int b = blockIdx.x;
    int w = threadIdx.x >> 5;
    int lane = threadIdx.x & 31;
    float acc = 0.0f;
#pragma unroll
    for (int k = lane; k < D2; k += 32)
        acc += d_h2[b * D2 + k] * W3[k * D3 + w];
#pragma unroll
    for (int off = 16; off; off >>= 1) acc += __shfl_xor_sync(0xFFFFFFFFu, acc, off);
    if (lane == 0) out[b * D3 + w] = acc + b3[w];
}

// ---------------- launch -----------------------------------------------------
extern "C" void kernel_launch(void* const* d_in, const int* in_sizes, int n_in,
                              void* d_out, int out_size)
{
    const float* x    = (const float*)d_in[0];
    const int*   ei   = (const int*)  d_in[1];
    const int*   batch= (const int*)  d_in[2];
    const float* Wl   = (const float*)d_in[3];
    const float* Wr   = (const float*)d_in[4];
    const float* att  = (const float*)d_in[5];
    const float* bias = (const float*)d_in[6];
    const float* W1   = (const float*)d_in[7];
    const float* b1   = (const float*)d_in[8];
    const float* W2   = (const float*)d_in[9];
    const float* b2   = (const float*)d_in[10];
    const float* W3   = (const float*)d_in[11];
    const float* b3   = (const float*)d_in[12];
    float* out = (float*)d_out;

    k_init<<<(Nn + 255) / 256, 256>>>();
    k_count<<<(Ee / 8 + 255) / 256, 256>>>(ei);
    k_bsum<<<NB, 1024>>>();
    k_scatter<<<NB, 1024>>>();
    k_fill<<<(Ee / 8 + 255) / 256, 256>>>(ei);
    k_transform<<<Nn / 32, 128>>>(x, Wl, Wr);
    k_node<<<Nn / 8, 256>>>(att, batch);
    k_mlp1<<<Bb, D1>>>(W1, b1, bias);
    k_mlp2<<<Bb / R2, 512>>>(W2, b2);
    k_mlp3<<<Bb, 128>>>(W3, b3, out);
}